// round 6
// baseline (speedup 1.0000x reference)
#include <cuda_runtime.h>
#include <cuda_bf16.h>
#include <math.h>
#include <stdint.h>

#define CB 16
#define CN 512
#define CD 256
#define CH 8
#define CDFF 1024
#define CL 2
#define NEG_INF_F (-1e9f)

// ---------------- scratch ----------------
static __device__ __align__(256) float g_x  [CB*CN*CD];
static __device__ __align__(256) float g_h  [CB*CN*CD];
static __device__ __align__(256) float g_qkv[CB*CN*768];   // also reused as GAT alpha fp32 (16MB < 25MB)
static __device__ __align__(256) float g_t  [CB*CN*CD];
static __device__ __align__(256) float g_ff [CB*CN*CDFF];
static __device__ __align__(256) float g_e1 [CB*CN];
static __device__ __align__(256) float g_e2 [CB*CN];
static __device__ __align__(256) float g_bias[768];

static __device__ __align__(256) __nv_bfloat16 g_x3 [CB*CN*768];
static __device__ __align__(256) __nv_bfloat16 g_o3 [CB*CN*768];
static __device__ __align__(256) __nv_bfloat16 g_ff3[CB*CN*3072];
static __device__ __align__(256) __nv_bfloat16 g_h3t[CB*CD*1536];
static __device__ __align__(256) __nv_bfloat16 g_q3 [CB*CH*CN*128];
static __device__ __align__(256) __nv_bfloat16 g_k3 [CB*CH*CN*128];
static __device__ __align__(256) __nv_bfloat16 g_v3t[CB*CH*32*1536];
static __device__ __align__(256) __nv_bfloat16 g_wb [1024*3072];
static __device__ __align__(256) __nv_bfloat16 g_wg3[CD*768];

__device__ __forceinline__ void bf_split_A(float v, __nv_bfloat16& a, __nv_bfloat16& b, __nv_bfloat16& c) {
    a = __float2bfloat16(v);
    b = __float2bfloat16(v - __bfloat162float(a));
    c = a;
}
__device__ __forceinline__ __nv_bfloat16 bf_lo(float v) {
    __nv_bfloat16 h = __float2bfloat16(v);
    return __float2bfloat16(v - __bfloat162float(h));
}
__device__ __forceinline__ void cpa16(uint32_t s, const void* g) {
    asm volatile("cp.async.cg.shared.global [%0], [%1], 16;" :: "r"(s), "l"(g));
}

// ---------------- cp.async double-buffered mma.sync bf16 GEMM ----------------
// C[128 x TN] per block; A [M,K3] bf16 OR Af32 [M,512] fp32 with on-the-fly [hi|lo|hi] split.
// B [N,K3] bf16 row-major. C = A@B^T (+bias, scale, act). Optional bf16x3 output C3.
template<int TN, int WM, int WN>
__global__ __launch_bounds__(256)
void gemm_mma(const __nv_bfloat16* __restrict__ A, const __nv_bfloat16* __restrict__ B,
              const float* __restrict__ bias, float* __restrict__ C,
              int lda, int ldb, int ldc, int K3,
              long strA, long strB, long sC1, long sC2, int divC,
              float scale, int act,
              __nv_bfloat16* __restrict__ C3, long sC31, long sC32, int ldc3, int seg3,
              const float* __restrict__ Af32, int lda32, long strA32)
{
    constexpr int BK = 64;
    constexpr int LDS = BK + 8;
    constexpr int MT = WM / 16;
    constexpr int NT = WN / 8;
    constexpr int WCOLS = TN / WN;
    constexpr int BITERS = TN / 32;

    extern __shared__ __nv_bfloat16 smem[];
    __nv_bfloat16* sA = smem;                 // [2][128][LDS]
    __nv_bfloat16* sB = smem + 2 * 128 * LDS; // [2][TN][LDS]

    const long z = blockIdx.z;
    if (Af32) Af32 += z * strA32;
    else      A    += z * strA;
    B += z * strB;
    C += (z / divC) * sC1 + (z % divC) * sC2;
    if (C3) C3 += (z / divC) * sC31 + (z % divC) * sC32;
    const int row0 = blockIdx.y * 128;
    const int col0 = blockIdx.x * TN;

    const int tid = threadIdx.x;
    const int w = tid >> 5, lane = tid & 31;
    const int wr = w / WCOLS, wc = w % WCOLS;
    const int gid = lane >> 2, tig = lane & 3;

    uint32_t sAu = (uint32_t)__cvta_generic_to_shared(sA);
    uint32_t sBu = (uint32_t)__cvta_generic_to_shared(sB);

    float acc[MT][NT][4];
#pragma unroll
    for (int mt = 0; mt < MT; mt++)
#pragma unroll
        for (int nt = 0; nt < NT; nt++)
#pragma unroll
            for (int i = 0; i < 4; i++) acc[mt][nt][i] = 0.f;

    const int nChunks = K3 / BK;

    auto issue = [&](int buf, int k0) {
        if (!Af32) {
#pragma unroll
            for (int i = 0; i < 4; i++) {
                const int idx = i * 256 + tid;
                const int r = idx >> 3, kc = (idx & 7) * 8;
                cpa16(sAu + (uint32_t)(((buf * 128 + r) * LDS + kc) * 2),
                      A + (long)(row0 + r) * lda + k0 + kc);
            }
        }
#pragma unroll
        for (int i = 0; i < BITERS; i++) {
            const int idx = i * 256 + tid;
            const int r = idx >> 3, kc = (idx & 7) * 8;
            cpa16(sBu + (uint32_t)(((buf * TN + r) * LDS + kc) * 2),
                  B + (long)(col0 + r) * ldb + k0 + kc);
        }
        asm volatile("cp.async.commit_group;");
    };

    issue(0, 0);
    for (int c = 0; c < nChunks; c++) {
        const int buf = c & 1;
        __syncthreads();
        if (c + 1 < nChunks) {
            issue(1 - buf, (c + 1) * BK);
            asm volatile("cp.async.wait_group 1;");
        } else {
            asm volatile("cp.async.wait_group 0;");
        }
        // on-the-fly fp32 -> bf16 split A fill for current chunk
        if (Af32) {
            const int k0 = c * BK;
            const int term = k0 >> 9;      // 0:hi 1:lo 2:hi  (BK=64 never crosses 512)
            const int src0 = k0 & 511;
            __nv_bfloat16* bA = sA + buf * 128 * LDS;
#pragma unroll
            for (int i = 0; i < 8; i++) {
                const int idx = i * 256 + tid;
                const int r = idx >> 4, cc = (idx & 15) * 4;
                float4 v4 = *reinterpret_cast<const float4*>(
                    Af32 + (long)(row0 + r) * lda32 + src0 + cc);
                __nv_bfloat162 p0, p1;
                if (term == 1) {
                    p0 = __nv_bfloat162(bf_lo(v4.x), bf_lo(v4.y));
                    p1 = __nv_bfloat162(bf_lo(v4.z), bf_lo(v4.w));
                } else {
                    p0 = __nv_bfloat162(__float2bfloat16(v4.x), __float2bfloat16(v4.y));
                    p1 = __nv_bfloat162(__float2bfloat16(v4.z), __float2bfloat16(v4.w));
                }
                *reinterpret_cast<__nv_bfloat162*>(&bA[r * LDS + cc]) = p0;
                *reinterpret_cast<__nv_bfloat162*>(&bA[r * LDS + cc + 2]) = p1;
            }
        }
        __syncthreads();

        const __nv_bfloat16* bA = sA + buf * 128 * LDS;
        const __nv_bfloat16* bB = sB + buf * TN * LDS;
#pragma unroll
        for (int kk = 0; kk < BK; kk += 16) {
            uint32_t af[MT][4], bfr[NT][2];
#pragma unroll
            for (int mt = 0; mt < MT; mt++) {
                const int r = wr * WM + mt * 16 + gid;
                af[mt][0] = *reinterpret_cast<const uint32_t*>(&bA[(r) * LDS + kk + tig * 2]);
                af[mt][1] = *reinterpret_cast<const uint32_t*>(&bA[(r + 8) * LDS + kk + tig * 2]);
                af[mt][2] = *reinterpret_cast<const uint32_t*>(&bA[(r) * LDS + kk + tig * 2 + 8]);
                af[mt][3] = *reinterpret_cast<const uint32_t*>(&bA[(r + 8) * LDS + kk + tig * 2 + 8]);
            }
#pragma unroll
            for (int nt = 0; nt < NT; nt++) {
                const int cidx = wc * WN + nt * 8 + gid;
                bfr[nt][0] = *reinterpret_cast<const uint32_t*>(&bB[cidx * LDS + kk + tig * 2]);
                bfr[nt][1] = *reinterpret_cast<const uint32_t*>(&bB[cidx * LDS + kk + tig * 2 + 8]);
            }
#pragma unroll
            for (int mt = 0; mt < MT; mt++)
#pragma unroll
                for (int nt = 0; nt < NT; nt++) {
                    asm volatile(
                        "mma.sync.aligned.m16n8k16.row.col.f32.bf16.bf16.f32 "
                        "{%0,%1,%2,%3}, {%4,%5,%6,%7}, {%8,%9}, {%0,%1,%2,%3};"
                        : "+f"(acc[mt][nt][0]), "+f"(acc[mt][nt][1]),
                          "+f"(acc[mt][nt][2]), "+f"(acc[mt][nt][3])
                        : "r"(af[mt][0]), "r"(af[mt][1]), "r"(af[mt][2]), "r"(af[mt][3]),
                          "r"(bfr[nt][0]), "r"(bfr[nt][1]));
                }
        }
    }

    // epilogue
#pragma unroll
    for (int mt = 0; mt < MT; mt++) {
#pragma unroll
        for (int nt = 0; nt < NT; nt++) {
            const int rloc = wr * WM + mt * 16 + gid;
            const int cloc = wc * WN + nt * 8 + tig * 2;
            const int cg = col0 + cloc;
            float b0 = bias ? bias[cg] : 0.f;
            float b1 = bias ? bias[cg + 1] : 0.f;
#pragma unroll
            for (int half = 0; half < 2; half++) {
                const int rg = row0 + rloc + half * 8;
                float v0 = acc[mt][nt][half * 2 + 0] * scale + b0;
                float v1 = acc[mt][nt][half * 2 + 1] * scale + b1;
                if (act == 1) { v0 = fmaxf(v0, 0.f); v1 = fmaxf(v1, 0.f); }
                else if (act == 2) {
                    v0 = (v0 > 0.f) ? v0 : expm1f(v0);
                    v1 = (v1 > 0.f) ? v1 : expm1f(v1);
                }
                *reinterpret_cast<float2*>(&C[(long)rg * ldc + cg]) = make_float2(v0, v1);
                if (C3) {
                    __nv_bfloat16 h0 = __float2bfloat16(v0);
                    __nv_bfloat16 l0 = __float2bfloat16(v0 - __bfloat162float(h0));
                    __nv_bfloat16 h1 = __float2bfloat16(v1);
                    __nv_bfloat16 l1 = __float2bfloat16(v1 - __bfloat162float(h1));
                    long base = (long)rg * ldc3 + cg;
                    *reinterpret_cast<__nv_bfloat162*>(&C3[base]) = __nv_bfloat162(h0, h1);
                    *reinterpret_cast<__nv_bfloat162*>(&C3[base + seg3]) = __nv_bfloat162(l0, l1);
                    *reinterpret_cast<__nv_bfloat162*>(&C3[base + 2 * seg3]) = __nv_bfloat162(h0, h1);
                }
            }
        }
    }
}

// ---------------- elementwise kernels ----------------

__global__ void embed_kernel(const int* __restrict__ node, const float* __restrict__ embed,
                             float* __restrict__ x, __nv_bfloat16* __restrict__ x3)
{
    const int row = blockIdx.x;
    const int d = threadIdx.x;
    const float v = embed[(long)node[row] * CD + d];
    x[(long)row * CD + d] = v;
    __nv_bfloat16 h0, h1, h2;
    bf_split_A(v, h0, h1, h2);
    x3[(long)row * 768 + d] = h0;
    x3[(long)row * 768 + 256 + d] = h1;
    x3[(long)row * 768 + 512 + d] = h2;
}

// in [R, C] (row stride irs) -> out [C, 3R] bf16 B-pattern [hi|hi|lo]
__global__ void tsplitB(const float* __restrict__ in, __nv_bfloat16* __restrict__ out,
                        int irs, int R, long sIn1, long sIn2, int divIn, long sOut)
{
    __shared__ float tile[128][33];
    const long z = blockIdx.z;
    in  += (z / divIn) * sIn1 + (z % divIn) * sIn2;
    out += z * sOut;
    const int r0 = blockIdx.x * 128, c0 = blockIdx.y * 32;
    for (int i = threadIdx.x; i < 128 * 32; i += 256) {
        int rr = i >> 5, cc = i & 31;
        tile[rr][cc] = in[(long)(r0 + rr) * irs + c0 + cc];
    }
    __syncthreads();
    for (int i = threadIdx.x; i < 32 * 128; i += 256) {
        int cc = i >> 7, rr = i & 127;
        float v = tile[rr][cc];
        __nv_bfloat16 hi = __float2bfloat16(v);
        __nv_bfloat16 lo = __float2bfloat16(v - __bfloat162float(hi));
        long ob = (long)(c0 + cc) * (3L * R) + (r0 + rr);
        out[ob] = hi; out[ob + R] = hi; out[ob + 2L * R] = lo;
    }
}

__global__ void qk_split(const float* __restrict__ qkv,
                         __nv_bfloat16* __restrict__ q3, __nv_bfloat16* __restrict__ k3)
{
    const int row = blockIdx.x;
    const int b = row >> 9, i = row & 511;
    const int d = threadIdx.x;
    const int h = d >> 5, dd = d & 31;
    const long base = ((long)(b * CH + h) * CN + i) * 128;
    const __nv_bfloat16 zero = __float2bfloat16(0.f);
    float qv = qkv[(long)row * 768 + d];
    float kv = qkv[(long)row * 768 + 256 + d];
    __nv_bfloat16 qh = __float2bfloat16(qv);
    __nv_bfloat16 ql = bf_lo(qv);
    __nv_bfloat16 kh = __float2bfloat16(kv);
    __nv_bfloat16 kl = bf_lo(kv);
    q3[base + dd] = qh;  q3[base + 32 + dd] = ql; q3[base + 64 + dd] = qh; q3[base + 96 + dd] = zero;
    k3[base + dd] = kh;  k3[base + 32 + dd] = kh; k3[base + 64 + dd] = kl; k3[base + 96 + dd] = zero;
}

__global__ void e12_kernel(const float* __restrict__ h, const float* __restrict__ a1,
                           const float* __restrict__ a2, float* __restrict__ e1, float* __restrict__ e2)
{
    const int row = blockIdx.x;
    const int d = threadIdx.x;
    __shared__ float s1[256], s2[256];
    const float hv = h[(long)row * CD + d];
    s1[d] = hv * a1[d];
    s2[d] = hv * a2[d];
    __syncthreads();
    for (int off = 128; off > 0; off >>= 1) {
        if (d < off) { s1[d] += s1[d + off]; s2[d] += s2[d + off]; }
        __syncthreads();
    }
    if (d == 0) { e1[row] = s1[0]; e2[row] = s2[0]; }
}

// GAT softmax -> alpha fp32
__global__ void gat_softmax_kernel(const float* __restrict__ e1, const float* __restrict__ e2,
                                   const int* __restrict__ edge, float* __restrict__ alpha)
{
    const int row = blockIdx.x;
    const int b = row / CN;
    const int t = threadIdx.x;
    __shared__ float red[256];
    const float ei = e1[row];
    float vals[2];
#pragma unroll
    for (int p = 0; p < 2; p++) {
        const int j = t + p * 256;
        float e = ei + e2[b * CN + j];
        e = (e >= 0.f) ? e : 0.2f * e;
        vals[p] = (edge[(long)row * CN + j] > 0) ? e : NEG_INF_F;
    }
    red[t] = fmaxf(vals[0], vals[1]);
    __syncthreads();
    for (int off = 128; off > 0; off >>= 1) { if (t < off) red[t] = fmaxf(red[t], red[t + off]); __syncthreads(); }
    const float m = red[0];
    __syncthreads();
    float ex[2] = {__expf(vals[0] - m), __expf(vals[1] - m)};
    red[t] = ex[0] + ex[1];
    __syncthreads();
    for (int off = 128; off > 0; off >>= 1) { if (t < off) red[t] += red[t + off]; __syncthreads(); }
    const float inv = 1.f / red[0];
#pragma unroll
    for (int p = 0; p < 2; p++) {
        const int j = t + p * 256;
        alpha[(long)row * CN + j] = ex[p] * inv;
    }
}

// MHA softmax: in-place fp32
__global__ void mha_softmax_kernel(float* __restrict__ s, const int* __restrict__ mask)
{
    const int r = blockIdx.x;
    const int b = r / (CH * CN);
    const int t = threadIdx.x;
    __shared__ float red[256];
    float* srow = s + (long)r * CN;
    float vals[2];
#pragma unroll
    for (int p = 0; p < 2; p++) {
        const int j = t + p * 256;
        vals[p] = srow[j] + (float)mask[b * CN + j] * NEG_INF_F;
    }
    red[t] = fmaxf(vals[0], vals[1]);
    __syncthreads();
    for (int off = 128; off > 0; off >>= 1) { if (t < off) red[t] = fmaxf(red[t], red[t + off]); __syncthreads(); }
    const float m = red[0];
    __syncthreads();
    float ex[2] = {__expf(vals[0] - m), __expf(vals[1] - m)};
    red[t] = ex[0] + ex[1];
    __syncthreads();
    for (int off = 128; off > 0; off >>= 1) { if (t < off) red[t] += red[t + off]; __syncthreads(); }
    const float inv = 1.f / red[0];
#pragma unroll
    for (int p = 0; p < 2; p++) {
        const int j = t + p * 256;
        srow[j] = ex[p] * inv;
    }
}

__global__ void scale_pe_kernel(float* __restrict__ x, __nv_bfloat16* __restrict__ x3)
{
    const int row = blockIdx.x;
    const int n = row % CN;
    const int d = threadIdx.x;
    const float expo = (2.0f * (float)(d >> 1)) / (float)CD;
    const float angle = (float)n * powf(10000.0f, -expo);
    const float pe = (d & 1) ? cosf(angle) : sinf(angle);
    const long idx = (long)row * CD + d;
    const float v = x[idx] * 16.0f + pe;
    x[idx] = v;
    __nv_bfloat16 h0, h1, h2;
    bf_split_A(v, h0, h1, h2);
    x3[(long)row * 768 + d] = h0;
    x3[(long)row * 768 + 256 + d] = h1;
    x3[(long)row * 768 + 512 + d] = h2;
}

__global__ void ln_kernel(const float* __restrict__ x, const float* __restrict__ delta,
                          const float* __restrict__ g, const float* __restrict__ bb,
                          float* __restrict__ out, __nv_bfloat16* __restrict__ x3)
{
    const int row = blockIdx.x;
    const int d = threadIdx.x;
    __shared__ float red[256];
    const long idx = (long)row * CD + d;
    const float v = x[idx] + delta[idx];
    red[d] = v;
    __syncthreads();
    for (int off = 128; off > 0; off >>= 1) { if (d < off) red[d] += red[d + off]; __syncthreads(); }
    const float mu = red[0] * (1.0f / CD);
    __syncthreads();
    const float c = v - mu;
    red[d] = c * c;
    __syncthreads();
    for (int off = 128; off > 0; off >>= 1) { if (d < off) red[d] += red[d + off]; __syncthreads(); }
    const float var = red[0] * (1.0f / CD);
    const float r = c * rsqrtf(var + 1e-6f) * g[d] + bb[d];
    out[idx] = r;
    if (x3) {
        __nv_bfloat16 h0, h1, h2;
        bf_split_A(r, h0, h1, h2);
        x3[(long)row * 768 + d] = h0;
        x3[(long)row * 768 + 256 + d] = h1;
        x3[(long)row * 768 + 512 + d] = h2;
    }
}

// ---------------- host ----------------
struct G3 { __nv_bfloat16* p; long s1; long s2; int ld; int seg; };
struct AF { const float* p; int ld; long str; };

static void launch_gemm(const __nv_bfloat16* A, const __nv_bfloat16* B, const float* bias, float* C,
                        int M, int N, int K3, int lda, int ldb, int ldc,
                        long sA, long sB, long sC1, long sC2, int divC,
                        float scale, int act, int batch, int tileN, G3 g3, AF af)
{
    if (tileN == 128) {
        dim3 g(N / 128, M / 128, batch);
        size_t sm = (2 * 128 + 2 * 128) * 72 * 2;
        gemm_mma<128, 64, 32><<<g, 256, sm>>>(A, B, bias, C, lda, ldb, ldc, K3,
            sA, sB, sC1, sC2, divC, scale, act, g3.p, g3.s1, g3.s2, g3.ld, g3.seg, af.p, af.ld, af.str);
    } else if (tileN == 64) {
        dim3 g(N / 64, M / 128, batch);
        size_t sm = (2 * 128 + 2 * 64) * 72 * 2;
        gemm_mma<64, 32, 32><<<g, 256, sm>>>(A, B, bias, C, lda, ldb, ldc, K3,
            sA, sB, sC1, sC2, divC, scale, act, g3.p, g3.s1, g3.s2, g3.ld, g3.seg, af.p, af.ld, af.str);
    } else {
        dim3 g(N / 32, M / 128, batch);
        size_t sm = (2 * 128 + 2 * 32) * 72 * 2;
        gemm_mma<32, 32, 16><<<g, 256, sm>>>(A, B, bias, C, lda, ldb, ldc, K3,
            sA, sB, sC1, sC2, divC, scale, act, g3.p, g3.s1, g3.s2, g3.ld, g3.seg, af.p, af.ld, af.str);
    }
}

extern "C" void kernel_launch(void* const* d_in, const int* in_sizes, int n_in,
                              void* d_out, int out_size)
{
    const int*   node  = (const int*)  d_in[0];
    const int*   edge  = (const int*)  d_in[1];
    const int*   mask  = (const int*)  d_in[2];
    const float* embed = (const float*)d_in[4];
    const float* Wg    = (const float*)d_in[5];
    const float* a1    = (const float*)d_in[6];
    const float* a2    = (const float*)d_in[7];
    const float* Wq    = (const float*)d_in[8];
    const float* bq    = (const float*)d_in[9];
    const float* Wk    = (const float*)d_in[10];
    const float* bk    = (const float*)d_in[11];
    const float* Wv    = (const float*)d_in[12];
    const float* bv    = (const float*)d_in[13];
    const float* Wo    = (const float*)d_in[14];
    const float* bo    = (const float*)d_in[15];
    const float* W1    = (const float*)d_in[16];
    const float* b1    = (const float*)d_in[17];
    const float* W2    = (const float*)d_in[18];
    const float* b2    = (const float*)d_in[19];
    const float* ln1g  = (const float*)d_in[20];
    const float* ln1b  = (const float*)d_in[21];
    const float* ln2g  = (const float*)d_in[22];
    const float* ln2b  = (const float*)d_in[23];

    cudaFuncSetAttribute((const void*)gemm_mma<128,64,32>, cudaFuncAttributeMaxDynamicSharedMemorySize, 75000);
    cudaFuncSetAttribute((const void*)gemm_mma<64,32,32>,  cudaFuncAttributeMaxDynamicSharedMemorySize, 60000);
    cudaFuncSetAttribute((const void*)gemm_mma<32,32,16>,  cudaFuncAttributeMaxDynamicSharedMemorySize, 50000);

    float *x, *h, *qkv, *t, *ff, *e1, *e2, *bias3;
    __nv_bfloat16 *x3, *o3, *ff3, *h3t, *q3, *k3, *v3t, *wb, *wg3;
    cudaGetSymbolAddress((void**)&x, g_x);     cudaGetSymbolAddress((void**)&h, g_h);
    cudaGetSymbolAddress((void**)&qkv, g_qkv); cudaGetSymbolAddress((void**)&t, g_t);
    cudaGetSymbolAddress((void**)&ff, g_ff);
    cudaGetSymbolAddress((void**)&e1, g_e1);   cudaGetSymbolAddress((void**)&e2, g_e2);
    cudaGetSymbolAddress((void**)&bias3, g_bias);
    cudaGetSymbolAddress((void**)&x3, g_x3);   cudaGetSymbolAddress((void**)&o3, g_o3);
    cudaGetSymbolAddress((void**)&ff3, g_ff3); cudaGetSymbolAddress((void**)&h3t, g_h3t);
    cudaGetSymbolAddress((void**)&q3, g_q3);   cudaGetSymbolAddress((void**)&k3, g_k3);
    cudaGetSymbolAddress((void**)&v3t, g_v3t); cudaGetSymbolAddress((void**)&wb, g_wb);
    cudaGetSymbolAddress((void**)&wg3, g_wg3);

    float* out_x    = (float*)d_out;
    float* out_attn = (float*)d_out + (long)CB * CN * CD;
    float* alpha    = qkv;   // reuse qkv buffer for GAT alpha fp32 (16MB < 25MB)

    const int M = CB * CN;
    const long ND = (long)CN * CD;
    const float inv_sqrt_dh = 0.17677669529663687f;
    const G3 no3 = {nullptr, 0, 0, 0, 0};
    const AF noaf = {nullptr, 0, 0};

    embed_kernel<<<M, CD>>>(node, embed, x, x3);
    tsplitB<<<dim3(2, 8, 1), 256>>>(Wg, wg3, CD, CD, 0, 0, 1, 0);

    for (int hop = 0; hop < 2; hop++) {
        launch_gemm(x3, wg3, nullptr, h, M, CD, 768, 768, 768, CD,
                    0, 0, 0, 0, 1, 1.f, 0, 1, 64, no3, noaf);
        tsplitB<<<dim3(4, 8, CB), 256>>>(h, h3t, CD, CN, ND, 0, 1, (long)CD * 1536);
        e12_kernel<<<M, CD>>>(h, a1, a2, e1, e2);
        gat_softmax_kernel<<<M, 256>>>(e1, e2, edge, alpha);
        // x = elu(alpha@h) with on-the-fly A split; emit x3
        G3 gx3 = {x3, (long)CN * 768, 0, 768, 256};
        AF aal = {alpha, CN, (long)CN * CN};
        launch_gemm(nullptr, h3t, nullptr, x, CN, CD, 1536, 0, 1536, CD,
                    0, (long)CD * 1536, ND, 0, 1, 1.f, 2, CB, 64, gx3, aal);
    }

    scale_pe_kernel<<<M, CD>>>(x, x3);

    for (int l = 0; l < CL; l++) {
        const long wOff = (long)l * CD * CD;
        tsplitB<<<dim3(2, 8, 1), 256>>>(Wq + wOff, wb, CD, CD, 0, 0, 1, 0);
        tsplitB<<<dim3(2, 8, 1), 256>>>(Wk + wOff, wb + 256 * 768, CD, CD, 0, 0, 1, 0);
        tsplitB<<<dim3(2, 8, 1), 256>>>(Wv + wOff, wb + 512 * 768, CD, CD, 0, 0, 1, 0);
        cudaMemcpyAsync(bias3,       bq + l * CD, CD * 4, cudaMemcpyDeviceToDevice, 0);
        cudaMemcpyAsync(bias3 + 256, bk + l * CD, CD * 4, cudaMemcpyDeviceToDevice, 0);
        cudaMemcpyAsync(bias3 + 512, bv + l * CD, CD * 4, cudaMemcpyDeviceToDevice, 0);

        launch_gemm(x3, wb, bias3, qkv, M, 768, 768, 768, 768, 768,
                    0, 0, 0, 0, 1, 1.f, 0, 1, 128, no3, noaf);

        qk_split<<<M, 256>>>(qkv, q3, k3);
        tsplitB<<<dim3(4, 1, CB * CH), 256>>>(qkv + 512, v3t, 768, CN,
                                              (long)CN * 768, 32, CH, 32L * 1536);

        launch_gemm(q3, k3, nullptr, out_attn, CN, CN, 128, 128, 128, CN,
                    (long)CN * 128, (long)CN * 128, (long)CN * CN, 0, 1,
                    inv_sqrt_dh, 0, CB * CH, 128, no3, noaf);

        mha_softmax_kernel<<<CB * CH * CN, 256>>>(out_attn, mask);

        // o = attn@v with on-the-fly A split from fp32 probs
        G3 go3 = {o3, (long)CN * 768, 32, 768, 256};
        AF aat = {out_attn, CN, (long)CN * CN};
        launch_gemm(nullptr, v3t, nullptr, t, CN, 32, 1536, 0, 1536, CD,
                    0, 32L * 1536, ND, 32, CH, 1.f, 0, CB * CH, 32, go3, aat);

        tsplitB<<<dim3(2, 8, 1), 256>>>(Wo + wOff, wb, CD, CD, 0, 0, 1, 0);
        launch_gemm(o3, wb, bo + l * CD, t, M, CD, 768, 768, 768, CD,
                    0, 0, 0, 0, 1, 1.f, 0, 1, 64, no3, noaf);
        ln_kernel<<<M, CD>>>(x, t, ln1g + l * CD, ln1b + l * CD, x, x3);

        tsplitB<<<dim3(2, 32, 1), 256>>>(W1 + (long)l * CD * CDFF, wb, CDFF, CD, 0, 0, 1, 0);
        G3 gff3 = {ff3, 0, 0, 3072, 1024};
        launch_gemm(x3, wb, b1 + l * CDFF, ff, M, CDFF, 768, 768, 768, CDFF,
                    0, 0, 0, 0, 1, 1.f, 1, 1, 128, gff3, noaf);
        tsplitB<<<dim3(8, 8, 1), 256>>>(W2 + (long)l * CDFF * CD, wb, CD, CDFF, 0, 0, 1, 0);
        launch_gemm(ff3, wb, b2 + l * CD, t, M, CD, 3072, 3072, 3072, CD,
                    0, 0, 0, 0, 1, 1.f, 0, 1, 64, no3, noaf);
        // final LN writes straight to d_out; x3 only needed if another layer follows
        const bool last = (l == CL - 1);
        ln_kernel<<<M, CD>>>(x, t, ln2g + l * CD, ln2b + l * CD,
                             last ? out_x : x, last ? nullptr : x3);
    }
}